// round 1
// baseline (speedup 1.0000x reference)
#include <cuda_runtime.h>
#include <cuda_bf16.h>
#include <math.h>

// ----------------------------------------------------------------------------
// Problem constants
// ----------------------------------------------------------------------------
#define Bz   16
#define Nn   392
#define Cc   512
#define Hh   16
#define HD   32
#define Mm   (Bz*Hh)          // 256
#define LF   196              // Nn/2
#define MLPH 2048
#define ROWS (Bz*Nn)          // 6272
#define WROW (Nn*LF)          // 76832  scores per m
#define KSEL 7448             // int(0.1*195)*392

// ----------------------------------------------------------------------------
// Scratch (static device globals; no allocation at runtime)
// ----------------------------------------------------------------------------
__device__ float g_h   [ROWS*Cc];
__device__ float g_qkv [ROWS*3*Cc];
__device__ float g_q   [Mm*Nn*HD];
__device__ float g_k   [Mm*Nn*HD];
__device__ float g_v   [Mm*Nn*HD];
__device__ float g_logits[(size_t)Mm*Nn*Nn];
__device__ unsigned g_scores[(size_t)Mm*WROW];
__device__ unsigned char g_mask[(size_t)Mm*WROW];
__device__ float g_o   [ROWS*Cc];
__device__ float g_x1  [ROWS*Cc];
__device__ float g_h2  [ROWS*Cc];
__device__ float g_mlp [ROWS*MLPH];
__device__ unsigned g_T[Mm];
__device__ int g_need[Mm];

// ----------------------------------------------------------------------------
// Reductions
// ----------------------------------------------------------------------------
__device__ __forceinline__ float warpMax(float v){
  #pragma unroll
  for (int o=16;o>0;o>>=1) v = fmaxf(v, __shfl_xor_sync(0xffffffffu, v, o));
  return v;
}
__device__ __forceinline__ float warpSum(float v){
  #pragma unroll
  for (int o=16;o>0;o>>=1) v += __shfl_xor_sync(0xffffffffu, v, o);
  return v;
}
__device__ __forceinline__ int warpSumI(int v){
  #pragma unroll
  for (int o=16;o>0;o>>=1) v += __shfl_xor_sync(0xffffffffu, v, o);
  return v;
}
template<int NW>
__device__ __forceinline__ float blockMax(float v, float* sw){
  int lane = threadIdx.x & 31, w = threadIdx.x >> 5;
  v = warpMax(v);
  if (lane==0) sw[w] = v;
  __syncthreads();
  float r = sw[0];
  #pragma unroll
  for (int i=1;i<NW;i++) r = fmaxf(r, sw[i]);
  __syncthreads();
  return r;
}
template<int NW>
__device__ __forceinline__ float blockSum(float v, float* sw){
  int lane = threadIdx.x & 31, w = threadIdx.x >> 5;
  v = warpSum(v);
  if (lane==0) sw[w] = v;
  __syncthreads();
  float r = 0.f;
  #pragma unroll
  for (int i=0;i<NW;i++) r += sw[i];
  __syncthreads();
  return r;
}

// ----------------------------------------------------------------------------
// JAX threefry2x32, key (0,42), partitionable 32-bit path: bits = o1 ^ o2 of
// threefry2x32(key, (hi=0, lo=idx))
// ----------------------------------------------------------------------------
__device__ __forceinline__ unsigned rotl32(unsigned x, int r){ return (x<<r)|(x>>(32-r)); }
__device__ __forceinline__ unsigned threefry_bits(unsigned idx){
  const unsigned k0 = 0u, k1 = 42u;
  const unsigned k2 = k0 ^ k1 ^ 0x1BD11BDAu;
  unsigned x0 = 0u + k0;
  unsigned x1 = idx + k1;
#define TFR(r) { x0 += x1; x1 = rotl32(x1,(r)); x1 ^= x0; }
  TFR(13) TFR(15) TFR(26) TFR(6)
  x0 += k1; x1 += k2 + 1u;
  TFR(17) TFR(29) TFR(16) TFR(24)
  x0 += k2; x1 += k0 + 2u;
  TFR(13) TFR(15) TFR(26) TFR(6)
  x0 += k0; x1 += k1 + 3u;
  TFR(17) TFR(29) TFR(16) TFR(24)
  x0 += k1; x1 += k2 + 4u;
  TFR(13) TFR(15) TFR(26) TFR(6)
  x0 += k2; x1 += k0 + 5u;
#undef TFR
  return x0 ^ x1;
}
__device__ __forceinline__ float gumbel_at(unsigned idx){
  unsigned bits = threefry_bits(idx);
  float f = __uint_as_float((bits >> 9) | 0x3f800000u) - 1.0f;
  const float tiny = 1.17549435e-38f;
  float u = fmaxf(tiny, f + tiny);
  return -logf(-logf(u));
}

// ----------------------------------------------------------------------------
// LayerNorm (one block per row, 256 threads, C=512)
// ----------------------------------------------------------------------------
__global__ void __launch_bounds__(256) ln_kernel(const float* __restrict__ x,
                                                 const float* __restrict__ w,
                                                 const float* __restrict__ bias,
                                                 float* __restrict__ out){
  int row = blockIdx.x, t = threadIdx.x;
  const float* xr = x + (size_t)row*Cc;
  __shared__ float sw[8];
  float a = xr[t], b = xr[t+256];
  float s = blockSum<8>(a+b, sw);
  float mu = s * (1.0f/512.0f);
  float da = a-mu, db = b-mu;
  float v = blockSum<8>(da*da + db*db, sw);
  float rstd = rsqrtf(v*(1.0f/512.0f) + 1e-5f);
  out[(size_t)row*Cc + t]     = da*rstd*w[t]     + bias[t];
  out[(size_t)row*Cc + t+256] = db*rstd*w[t+256] + bias[t+256];
}

// ----------------------------------------------------------------------------
// GEMM: C[M,N] = A[M,K] @ B[K,N] + bias (+gelu) (+residual)
// 128x128 tile, BK=8, 256 threads, 8x8 per thread.
// ----------------------------------------------------------------------------
__global__ void __launch_bounds__(256) gemm_kernel(const float* __restrict__ A,
                                                   const float* __restrict__ Bw,
                                                   const float* __restrict__ bias,
                                                   const float* __restrict__ res,
                                                   float* __restrict__ C,
                                                   int M, int N, int K, int act){
  __shared__ float As[8][128];
  __shared__ float Bs[8][128];
  int bm = blockIdx.y*128, bn = blockIdx.x*128;
  int tid = threadIdx.x;
  int tr = tid >> 4, tc = tid & 15;
  float acc[8][8];
  #pragma unroll
  for (int i=0;i<8;i++)
    #pragma unroll
    for (int j=0;j<8;j++) acc[i][j]=0.f;

  for (int k0=0;k0<K;k0+=8){
    #pragma unroll
    for (int q=0;q<4;q++){
      int lin = tid + 256*q;
      int ml = lin >> 3, kl = lin & 7;
      As[kl][ml] = A[(size_t)(bm+ml)*K + k0 + kl];
      int nl = lin & 127, kb = lin >> 7;
      Bs[kb][nl] = Bw[(size_t)(k0+kb)*N + bn + nl];
    }
    __syncthreads();
    #pragma unroll
    for (int kk=0;kk<8;kk++){
      float4 a0 = *(const float4*)&As[kk][tr*8];
      float4 a1 = *(const float4*)&As[kk][tr*8+4];
      float4 b0 = *(const float4*)&Bs[kk][tc*8];
      float4 b1 = *(const float4*)&Bs[kk][tc*8+4];
      float av[8] = {a0.x,a0.y,a0.z,a0.w,a1.x,a1.y,a1.z,a1.w};
      float bv[8] = {b0.x,b0.y,b0.z,b0.w,b1.x,b1.y,b1.z,b1.w};
      #pragma unroll
      for (int i=0;i<8;i++)
        #pragma unroll
        for (int j=0;j<8;j++) acc[i][j] += av[i]*bv[j];
    }
    __syncthreads();
  }
  #pragma unroll
  for (int i=0;i<8;i++){
    int mr = bm + tr*8 + i;
    #pragma unroll
    for (int j=0;j<8;j++){
      int nc = bn + tc*8 + j;
      float v = acc[i][j] + bias[nc];
      if (act==1) v = 0.5f*v*(1.0f + erff(v*0.70710678118654752440f));
      if (res) v += res[(size_t)mr*N + nc];
      C[(size_t)mr*N + nc] = v;
    }
  }
}

// ----------------------------------------------------------------------------
// QKV reorder: [row=b*392+i][3*512] -> Q/K/V [m=b*16+h][i][d]
// ----------------------------------------------------------------------------
__global__ void reorder_qkv(){
  int idx = blockIdx.x*blockDim.x + threadIdx.x;
  if (idx >= ROWS*3*Cc) return;
  int r = idx / (3*Cc), c = idx % (3*Cc);
  int which = c >> 9;
  int cc = c & 511;
  int h = cc >> 5, d = cc & 31;
  int b = r / Nn, i = r % Nn;
  float v = g_qkv[idx];
  size_t dst = ((size_t)((b*Hh+h)*Nn + i))*HD + d;
  if (which==0) g_q[dst]=v; else if (which==1) g_k[dst]=v; else g_v[dst]=v;
}

// ----------------------------------------------------------------------------
// Per (m,i): compute logits row, softmax stats, drop-out scores (sortable u32)
// 128 threads per block.
// ----------------------------------------------------------------------------
__global__ void __launch_bounds__(128) score_kernel(){
  int blk = blockIdx.x;
  int m = blk / Nn, i = blk % Nn;
  int tid = threadIdx.x;
  __shared__ float q[HD];
  __shared__ float l[Nn];
  __shared__ float spb[LF];
  __shared__ float sw[4];
  if (tid < HD) q[tid] = g_q[((size_t)m*Nn + i)*HD + tid];
  __syncthreads();
  const float scale = 0.17677669529663687f; // 32^-0.5
  for (int j=tid; j<Nn; j+=128){
    const float4* kp = (const float4*)(g_k + ((size_t)m*Nn + j)*HD);
    const float4* qp = (const float4*)q;
    float acc = 0.f;
    #pragma unroll
    for (int t4=0;t4<8;t4++){
      float4 kv = kp[t4], qv = qp[t4];
      acc += kv.x*qv.x + kv.y*qv.y + kv.z*qv.z + kv.w*qv.w;
    }
    l[j] = acc*scale;
  }
  __syncthreads();
  for (int j=tid; j<Nn; j+=128) g_logits[(size_t)blk*Nn + j] = l[j];

  float lm = -3.4e38f;
  for (int j=tid; j<Nn; j+=128) lm = fmaxf(lm, l[j]);
  float mx = blockMax<4>(lm, sw);
  float ls = 0.f;
  for (int j=tid; j<Nn; j+=128) ls += expf(l[j]-mx);
  float sum = blockSum<4>(ls, sw);

  int side  = (i >= LF);
  int same  = side ? LF : 0;
  int cross = side ? 0  : LF;
  float cm = -3.4e38f;
  for (int jl=tid; jl<LF; jl+=128) cm = fmaxf(cm, l[cross+jl]);
  float cmx = blockMax<4>(cm, sw);
  float aqmax = expf(cmx - mx)/sum + 1e-6f;

  int diag = i - same;
  float ssum = 0.f;
  for (int jl=tid; jl<LF; jl+=128){
    float s = expf(l[same+jl]-mx)/sum;
    float sp = (jl==diag) ? 0.0f : (s + 1e-6f);
    spb[jl] = sp;
    ssum += sp;
  }
  float S = blockSum<4>(ssum, sw);
  for (int jl=tid; jl<LF; jl+=128){
    float sc;
    if (jl==diag) sc = __int_as_float(0xff800000); // -inf
    else {
      float w = (spb[jl]/S) * aqmax;
      unsigned gi = (unsigned)(m*WROW + i*LF + jl);
      sc = logf(w) + gumbel_at(gi);
    }
    unsigned b = __float_as_uint(sc);
    b = (b & 0x80000000u) ? ~b : (b | 0x80000000u);
    g_scores[(size_t)m*WROW + i*LF + jl] = b;
  }
}

// ----------------------------------------------------------------------------
// Per m: radix-select the KSEL-th largest score (as sortable u32), count > T
// ----------------------------------------------------------------------------
__global__ void __launch_bounds__(256) select_kernel(){
  int m = blockIdx.x, tid = threadIdx.x;
  const unsigned* row = g_scores + (size_t)m*WROW;
  __shared__ unsigned hist[256];
  __shared__ unsigned s_prefix;
  __shared__ int s_krem;
  unsigned prefix = 0; int krem = KSEL;
  for (int pass=0; pass<4; pass++){
    int shift = 24 - 8*pass;
    unsigned hm = pass ? (0xFFFFFFFFu << (shift+8)) : 0u;
    hist[tid] = 0;
    __syncthreads();
    for (int idx=tid; idx<WROW; idx+=256){
      unsigned u = row[idx];
      if ((u & hm) == prefix) atomicAdd(&hist[(u>>shift)&0xFFu], 1u);
    }
    __syncthreads();
    if (tid==0){
      int cum = 0, b = 255;
      for (; b>=0; b--){ cum += (int)hist[b]; if (cum >= krem) break; }
      int above = cum - (int)hist[b];
      s_prefix = prefix | ((unsigned)b << shift);
      s_krem = krem - above;
    }
    __syncthreads();
    prefix = s_prefix; krem = s_krem;
    __syncthreads();
  }
  int cg = 0;
  for (int idx=tid; idx<WROW; idx+=256) if (row[idx] > prefix) cg++;
  __shared__ int csum[8];
  cg = warpSumI(cg);
  if ((tid&31)==0) csum[tid>>5] = cg;
  __syncthreads();
  if (tid==0){
    int t = 0;
    for (int w=0;w<8;w++) t += csum[w];
    g_T[m] = prefix;
    g_need[m] = KSEL - t;
  }
}

// ----------------------------------------------------------------------------
// Per m: build mask; equals-to-threshold selected in index order (stable topk)
// ----------------------------------------------------------------------------
__global__ void __launch_bounds__(256) mask_kernel(){
  int m = blockIdx.x, tid = threadIdx.x;
  unsigned T = g_T[m]; int need = g_need[m];
  const unsigned* row = g_scores + (size_t)m*WROW;
  unsigned char* mrow = g_mask + (size_t)m*WROW;
  __shared__ int running;
  __shared__ int wtot[8];
  if (tid==0) running = 0;
  __syncthreads();
  int lane = tid & 31, w = tid >> 5;
  for (int base=0; base<WROW; base+=256){
    int idx = base + tid;
    bool valid = idx < WROW;
    unsigned u = valid ? row[idx] : 0u;
    bool gt = valid && (u > T);
    bool eq = valid && (u == T);
    unsigned bal = __ballot_sync(0xffffffffu, eq);
    int lrank = __popc(bal & ((1u<<lane)-1u));
    if (lane==0) wtot[w] = __popc(bal);
    __syncthreads();
    int off = running;
    for (int ww=0; ww<w; ww++) off += wtot[ww];
    bool sel = eq && (off + lrank < need);
    if (valid) mrow[idx] = (gt || sel) ? 1 : 0;
    __syncthreads();
    if (tid==0){
      int tot = 0;
      for (int ww=0; ww<8; ww++) tot += wtot[ww];
      running += tot;
    }
    __syncthreads();
  }
}

// ----------------------------------------------------------------------------
// Per (m,i): masked softmax + P@V -> o (written in (B,N,C) layout)
// 256 threads.
// ----------------------------------------------------------------------------
__global__ void __launch_bounds__(256) attn_kernel(){
  int blk = blockIdx.x;
  int m = blk / Nn, i = blk % Nn;
  int tid = threadIdx.x;
  __shared__ float l[Nn];
  __shared__ float sw[8];
  __shared__ float red[8][32];
  int side = (i >= LF);
  int same = side ? LF : 0;
  const unsigned char* mrow = g_mask + (size_t)m*WROW + (size_t)i*LF;
  for (int j=tid; j<Nn; j+=256){
    float v = g_logits[(size_t)blk*Nn + j];
    int jl = j - same;
    if (jl >= 0 && jl < LF && mrow[jl]) v = __int_as_float(0xff800000);
    l[j] = v;
  }
  __syncthreads();
  float lm = -3.4e38f;
  for (int j=tid; j<Nn; j+=256) lm = fmaxf(lm, l[j]);
  float mx = blockMax<8>(lm, sw);
  float ls = 0.f;
  for (int j=tid; j<Nn; j+=256){
    float e = expf(l[j]-mx);
    l[j] = e;
    ls += e;
  }
  float sum = blockSum<8>(ls, sw);
  float inv = 1.0f/sum;
  for (int j=tid; j<Nn; j+=256) l[j] *= inv;
  __syncthreads();

  int d = tid & 31, g = tid >> 5;
  float acc = 0.f;
  for (int j=g; j<Nn; j+=8)
    acc += l[j] * g_v[((size_t)m*Nn + j)*HD + d];
  red[g][d] = acc;
  __syncthreads();
  if (tid < 32){
    float r = 0.f;
    #pragma unroll
    for (int gg=0; gg<8; gg++) r += red[gg][tid];
    int b = m >> 4, h = m & 15;
    g_o[((size_t)(b*Nn + i))*Cc + h*HD + tid] = r;
  }
}

// ----------------------------------------------------------------------------
// Launch
// ----------------------------------------------------------------------------
extern "C" void kernel_launch(void* const* d_in, const int* in_sizes, int n_in,
                              void* d_out, int out_size){
  const float* x      = (const float*)d_in[0];
  const float* n1w    = (const float*)d_in[1];
  const float* n1b    = (const float*)d_in[2];
  const float* qkv_w  = (const float*)d_in[3];
  const float* qkv_b  = (const float*)d_in[4];
  const float* proj_w = (const float*)d_in[5];
  const float* proj_b = (const float*)d_in[6];
  const float* n2w    = (const float*)d_in[7];
  const float* n2b    = (const float*)d_in[8];
  const float* fc1_w  = (const float*)d_in[9];
  const float* fc1_b  = (const float*)d_in[10];
  const float* fc2_w  = (const float*)d_in[11];
  const float* fc2_b  = (const float*)d_in[12];
  float* out = (float*)d_out;

  float *p_h, *p_qkv, *p_o, *p_x1, *p_h2, *p_mlp;
  cudaGetSymbolAddress((void**)&p_h,   g_h);
  cudaGetSymbolAddress((void**)&p_qkv, g_qkv);
  cudaGetSymbolAddress((void**)&p_o,   g_o);
  cudaGetSymbolAddress((void**)&p_x1,  g_x1);
  cudaGetSymbolAddress((void**)&p_h2,  g_h2);
  cudaGetSymbolAddress((void**)&p_mlp, g_mlp);

  // 1) LN1
  ln_kernel<<<ROWS, 256>>>(x, n1w, n1b, p_h);
  // 2) QKV GEMM: [6272,512] @ [512,1536]
  gemm_kernel<<<dim3(3*Cc/128, ROWS/128), 256>>>(p_h, qkv_w, qkv_b, nullptr, p_qkv,
                                                 ROWS, 3*Cc, Cc, 0);
  // 3) reorder to per-head Q/K/V
  reorder_qkv<<<(ROWS*3*Cc + 255)/256, 256>>>();
  // 4) logits + dropout scores
  score_kernel<<<Mm*Nn, 128>>>();
  // 5) per-m top-k threshold
  select_kernel<<<Mm, 256>>>();
  // 6) per-m mask with stable tie-break
  mask_kernel<<<Mm, 256>>>();
  // 7) masked softmax + AV
  attn_kernel<<<Mm*Nn, 256>>>();
  // 8) proj + residual(x)
  gemm_kernel<<<dim3(Cc/128, ROWS/128), 256>>>(p_o, proj_w, proj_b, x, p_x1,
                                               ROWS, Cc, Cc, 0);
  // 9) LN2
  ln_kernel<<<ROWS, 256>>>(p_x1, n2w, n2b, p_h2);
  // 10) fc1 + exact gelu
  gemm_kernel<<<dim3(MLPH/128, ROWS/128), 256>>>(p_h2, fc1_w, fc1_b, nullptr, p_mlp,
                                                 ROWS, MLPH, Cc, 1);
  // 11) fc2 + residual(x1) -> out
  gemm_kernel<<<dim3(Cc/128, ROWS/128), 256>>>(p_mlp, fc2_w, fc2_b, p_x1, out,
                                               ROWS, Cc, MLPH, 0);
}

// round 2
// speedup vs baseline: 1.8736x; 1.8736x over previous
#include <cuda_runtime.h>
#include <cuda_bf16.h>
#include <math.h>

// ----------------------------------------------------------------------------
// Problem constants
// ----------------------------------------------------------------------------
#define Bz   16
#define Nn   392
#define Cc   512
#define Hh   16
#define HD   32
#define Mm   (Bz*Hh)          // 256
#define LF   196              // Nn/2
#define MLPH 2048
#define ROWS (Bz*Nn)          // 6272
#define WROW (Nn*LF)          // 76832  scores per m
#define KSEL 7448             // int(0.1*195)*392
#define NEGINF __int_as_float(0xff800000)

// ----------------------------------------------------------------------------
// Scratch (static device globals; no allocation at runtime)
// ----------------------------------------------------------------------------
__device__ float g_h   [ROWS*Cc];
__device__ float g_qkv [ROWS*3*Cc];
__device__ float g_q   [Mm*Nn*HD];
__device__ float g_k   [Mm*Nn*HD];
__device__ float g_v   [Mm*Nn*HD];
__device__ float g_logits[(size_t)Mm*Nn*Nn];
__device__ unsigned g_scores[(size_t)Mm*WROW];
__device__ unsigned char g_mask[(size_t)Mm*WROW];
__device__ float g_o   [ROWS*Cc];
__device__ float g_x1  [ROWS*Cc];
__device__ float g_h2  [ROWS*Cc];
__device__ float g_mlp [ROWS*MLPH];
__device__ unsigned g_T[Mm];
__device__ int g_need[Mm];

// ----------------------------------------------------------------------------
// Reductions
// ----------------------------------------------------------------------------
__device__ __forceinline__ float warpMax(float v){
  #pragma unroll
  for (int o=16;o>0;o>>=1) v = fmaxf(v, __shfl_xor_sync(0xffffffffu, v, o));
  return v;
}
__device__ __forceinline__ float warpSum(float v){
  #pragma unroll
  for (int o=16;o>0;o>>=1) v += __shfl_xor_sync(0xffffffffu, v, o);
  return v;
}
__device__ __forceinline__ int warpSumI(int v){
  #pragma unroll
  for (int o=16;o>0;o>>=1) v += __shfl_xor_sync(0xffffffffu, v, o);
  return v;
}
template<int NW>
__device__ __forceinline__ float blockSum(float v, float* sw){
  int lane = threadIdx.x & 31, w = threadIdx.x >> 5;
  v = warpSum(v);
  if (lane==0) sw[w] = v;
  __syncthreads();
  float r = 0.f;
  #pragma unroll
  for (int i=0;i<NW;i++) r += sw[i];
  __syncthreads();
  return r;
}

// ----------------------------------------------------------------------------
// JAX threefry2x32, key (0,42), partitionable 32-bit path
// ----------------------------------------------------------------------------
__device__ __forceinline__ unsigned rotl32(unsigned x, int r){ return (x<<r)|(x>>(32-r)); }
__device__ __forceinline__ unsigned threefry_bits(unsigned idx){
  const unsigned k0 = 0u, k1 = 42u;
  const unsigned k2 = k0 ^ k1 ^ 0x1BD11BDAu;
  unsigned x0 = 0u + k0;
  unsigned x1 = idx + k1;
#define TFR(r) { x0 += x1; x1 = rotl32(x1,(r)); x1 ^= x0; }
  TFR(13) TFR(15) TFR(26) TFR(6)
  x0 += k1; x1 += k2 + 1u;
  TFR(17) TFR(29) TFR(16) TFR(24)
  x0 += k2; x1 += k0 + 2u;
  TFR(13) TFR(15) TFR(26) TFR(6)
  x0 += k0; x1 += k1 + 3u;
  TFR(17) TFR(29) TFR(16) TFR(24)
  x0 += k1; x1 += k2 + 4u;
  TFR(13) TFR(15) TFR(26) TFR(6)
  x0 += k2; x1 += k0 + 5u;
#undef TFR
  return x0 ^ x1;
}
__device__ __forceinline__ float gumbel_at(unsigned idx){
  unsigned bits = threefry_bits(idx);
  float f = __uint_as_float((bits >> 9) | 0x3f800000u) - 1.0f;
  const float tiny = 1.17549435e-38f;
  float u = fmaxf(tiny, f + tiny);
  return -logf(-logf(u));
}

// ----------------------------------------------------------------------------
// LayerNorm (one block per row, 256 threads, C=512)
// ----------------------------------------------------------------------------
__global__ void __launch_bounds__(256) ln_kernel(const float* __restrict__ x,
                                                 const float* __restrict__ w,
                                                 const float* __restrict__ bias,
                                                 float* __restrict__ out){
  int row = blockIdx.x, t = threadIdx.x;
  const float* xr = x + (size_t)row*Cc;
  __shared__ float sw[8];
  float a = xr[t], b = xr[t+256];
  float s = blockSum<8>(a+b, sw);
  float mu = s * (1.0f/512.0f);
  float da = a-mu, db = b-mu;
  float v = blockSum<8>(da*da + db*db, sw);
  float rstd = rsqrtf(v*(1.0f/512.0f) + 1e-5f);
  out[(size_t)row*Cc + t]     = da*rstd*w[t]     + bias[t];
  out[(size_t)row*Cc + t+256] = db*rstd*w[t+256] + bias[t+256];
}

// ----------------------------------------------------------------------------
// tf32 tensor-core GEMM: C[M,N] = A[M,K] @ B[K,N] + bias (+gelu) (+residual)
// 128x128 tile, BK=16, 256 threads (8 warps, 2x4), mma.m16n8k8.tf32,
// cp.async double-buffered. A smem pad 20, B smem pad 136 (bank-conflict-free).
// ----------------------------------------------------------------------------
__device__ __forceinline__ void cp16(float* dst, const float* src){
  unsigned d = (unsigned)__cvta_generic_to_shared(dst);
  asm volatile("cp.async.ca.shared.global [%0], [%1], 16;\n" :: "r"(d), "l"(src));
}
__device__ __forceinline__ unsigned f2tf(float x){
  unsigned r; asm("cvt.rna.tf32.f32 %0, %1;\n":"=r"(r):"f"(x)); return r;
}
__device__ __forceinline__ void mma_tf32(float* c, const unsigned* a, const unsigned* b){
  asm volatile(
    "mma.sync.aligned.m16n8k8.row.col.f32.tf32.tf32.f32 "
    "{%0,%1,%2,%3},{%4,%5,%6,%7},{%8,%9},{%0,%1,%2,%3};\n"
    : "+f"(c[0]),"+f"(c[1]),"+f"(c[2]),"+f"(c[3])
    : "r"(a[0]),"r"(a[1]),"r"(a[2]),"r"(a[3]),"r"(b[0]),"r"(b[1]));
}

#define APAD 20
#define BPAD 136

__global__ void __launch_bounds__(256) gemm_tf32(const float* __restrict__ A,
                                                 const float* __restrict__ Bw,
                                                 const float* __restrict__ bias,
                                                 const float* __restrict__ res,
                                                 float* __restrict__ C,
                                                 int M, int N, int K, int act){
  __shared__ float As[2][128*APAD];
  __shared__ float Bs[2][16*BPAD];
  const int tid = threadIdx.x;
  const int lane = tid & 31, wid = tid >> 5;
  const int wm = wid >> 2, wn = wid & 3;       // 2 x 4 warp grid
  const int bm = blockIdx.y*128, bn = blockIdx.x*128;

  float acc[16][4];
  #pragma unroll
  for (int i=0;i<16;i++){ acc[i][0]=0.f; acc[i][1]=0.f; acc[i][2]=0.f; acc[i][3]=0.f; }

  const int nT = K >> 4;

  // ---- stage loader
  auto load_stage = [&](int t, int buf){
    int k0 = t << 4;
    #pragma unroll
    for (int r=0;r<2;r++){
      int i = tid + 256*r;
      int arow = i >> 2, ac = (i & 3) << 2;
      cp16(&As[buf][arow*APAD + ac], A + (size_t)(bm+arow)*K + k0 + ac);
      int brow = i >> 5, bc = (i & 31) << 2;
      cp16(&Bs[buf][brow*BPAD + bc], Bw + (size_t)(k0+brow)*N + bn + bc);
    }
    asm volatile("cp.async.commit_group;\n");
  };

  load_stage(0, 0);
  for (int t=0; t<nT; t++){
    if (t+1 < nT) load_stage(t+1, (t+1)&1);
    if (t+1 < nT) asm volatile("cp.async.wait_group 1;\n");
    else          asm volatile("cp.async.wait_group 0;\n");
    __syncthreads();
    const float* as = As[t&1];
    const float* bs = Bs[t&1];
    #pragma unroll
    for (int ks=0; ks<16; ks+=8){
      unsigned a[4][4], b[4][2];
      #pragma unroll
      for (int mt=0;mt<4;mt++){
        int r0 = wm*64 + mt*16 + (lane>>2);
        int cc = ks + (lane&3);
        a[mt][0] = f2tf(as[r0*APAD + cc]);
        a[mt][1] = f2tf(as[(r0+8)*APAD + cc]);
        a[mt][2] = f2tf(as[r0*APAD + cc + 4]);
        a[mt][3] = f2tf(as[(r0+8)*APAD + cc + 4]);
      }
      #pragma unroll
      for (int nt=0;nt<4;nt++){
        int cn = wn*32 + nt*8 + (lane>>2);
        b[nt][0] = f2tf(bs[(ks + (lane&3))*BPAD + cn]);
        b[nt][1] = f2tf(bs[(ks + 4 + (lane&3))*BPAD + cn]);
      }
      #pragma unroll
      for (int mt=0;mt<4;mt++)
        #pragma unroll
        for (int nt=0;nt<4;nt++)
          mma_tf32(acc[mt*4+nt], a[mt], b[nt]);
    }
    __syncthreads();
  }

  // ---- epilogue
  #pragma unroll
  for (int mt=0;mt<4;mt++){
    #pragma unroll
    for (int nt=0;nt<4;nt++){
      float* c = acc[mt*4+nt];
      int gm = bm + wm*64 + mt*16 + (lane>>2);
      int gn = bn + wn*32 + nt*8 + ((lane&3)<<1);
      float b0 = bias[gn], b1 = bias[gn+1];
      #pragma unroll
      for (int hrow=0; hrow<2; hrow++){
        int gr = gm + hrow*8;
        float v0 = c[hrow*2+0] + b0;
        float v1 = c[hrow*2+1] + b1;
        if (act==1){
          v0 = 0.5f*v0*(1.0f + erff(v0*0.70710678118654752440f));
          v1 = 0.5f*v1*(1.0f + erff(v1*0.70710678118654752440f));
        }
        if (res){
          v0 += res[(size_t)gr*N + gn];
          v1 += res[(size_t)gr*N + gn+1];
        }
        C[(size_t)gr*N + gn]   = v0;
        C[(size_t)gr*N + gn+1] = v1;
      }
    }
  }
}

// ----------------------------------------------------------------------------
// QKV reorder: [row=b*392+i][3*512] -> Q/K/V [m=b*16+h][i][d]
// ----------------------------------------------------------------------------
__global__ void reorder_qkv(){
  int idx = blockIdx.x*blockDim.x + threadIdx.x;
  if (idx >= ROWS*3*Cc) return;
  int r = idx / (3*Cc), c = idx % (3*Cc);
  int which = c >> 9;
  int cc = c & 511;
  int h = cc >> 5, d = cc & 31;
  int b = r / Nn, i = r % Nn;
  float v = g_qkv[idx];
  size_t dst = ((size_t)((b*Hh+h)*Nn + i))*HD + d;
  if (which==0) g_q[dst]=v; else if (which==1) g_k[dst]=v; else g_v[dst]=v;
}

// ----------------------------------------------------------------------------
// score kernel: block = (m, tile of 8 query rows). K read once per tile.
// Per-warp softmax stats + dropout score generation.
// ----------------------------------------------------------------------------
__global__ void __launch_bounds__(256) score_kernel(){
  int blk = blockIdx.x;
  int m = blk / 49, it = blk % 49;
  int i0 = it*8;
  int tid = threadIdx.x, lane = tid & 31, w = tid >> 5;
  __shared__ float q[8][32];
  __shared__ float l[8][Nn];

  { // load 8 q rows
    int i = tid >> 5, d = tid & 31;
    q[i][d] = g_q[((size_t)m*Nn + i0 + i)*HD + d];
  }
  __syncthreads();

  const float scale = 0.17677669529663687f; // 32^-0.5
  for (int j=tid; j<Nn; j+=256){
    float4 kv[8];
    const float4* kp = (const float4*)(g_k + ((size_t)m*Nn + j)*HD);
    #pragma unroll
    for (int t=0;t<8;t++) kv[t] = kp[t];
    #pragma unroll
    for (int i=0;i<8;i++){
      const float4* qp = (const float4*)q[i];
      float acc = 0.f;
      #pragma unroll
      for (int t=0;t<8;t++){
        float4 qv = qp[t];
        acc += kv[t].x*qv.x + kv[t].y*qv.y + kv[t].z*qv.z + kv[t].w*qv.w;
      }
      l[i][j] = acc*scale;
    }
  }
  __syncthreads();

  // dump logits
  for (int idx=tid; idx<8*Nn; idx+=256){
    int i = idx/Nn, j = idx%Nn;
    g_logits[((size_t)m*Nn + i0 + i)*Nn + j] = l[i][j];
  }

  // per-warp stats (warp w owns row i0+w)
  int i = i0 + w;
  float* li = l[w];
  float lm = -3.4e38f;
  for (int j=lane; j<Nn; j+=32) lm = fmaxf(lm, li[j]);
  float mx = warpMax(lm);
  float ls = 0.f;
  for (int j=lane; j<Nn; j+=32) ls += expf(li[j]-mx);
  float sum = warpSum(ls);

  int side = (i >= LF);
  int same = side ? LF : 0;
  int cross = side ? 0 : LF;
  float cm = -3.4e38f;
  for (int jl=lane; jl<LF; jl+=32) cm = fmaxf(cm, li[cross+jl]);
  float cmx = warpMax(cm);
  float aqmax = expf(cmx - mx)/sum + 1e-6f;

  int diag = i - same;
  float ssum = 0.f;
  for (int jl=lane; jl<LF; jl+=32){
    float s = expf(li[same+jl]-mx)/sum;
    ssum += (jl==diag) ? 0.f : (s + 1e-6f);
  }
  float S = warpSum(ssum);

  for (int jl=lane; jl<LF; jl+=32){
    float sc;
    if (jl==diag) sc = NEGINF;
    else {
      float s = expf(li[same+jl]-mx)/sum;
      float wv = ((s + 1e-6f)/S) * aqmax;
      unsigned gi = (unsigned)(m*WROW + i*LF + jl);
      sc = logf(wv) + gumbel_at(gi);
    }
    unsigned bb = __float_as_uint(sc);
    bb = (bb & 0x80000000u) ? ~bb : (bb | 0x80000000u);
    g_scores[(size_t)m*WROW + (size_t)i*LF + jl] = bb;
  }
}

// ----------------------------------------------------------------------------
// Per m: radix-select the KSEL-th largest score, count > T
// ----------------------------------------------------------------------------
__global__ void __launch_bounds__(256) select_kernel(){
  int m = blockIdx.x, tid = threadIdx.x;
  const unsigned* row = g_scores + (size_t)m*WROW;
  __shared__ unsigned hist[256];
  __shared__ unsigned s_prefix;
  __shared__ int s_krem;
  unsigned prefix = 0; int krem = KSEL;
  for (int pass=0; pass<4; pass++){
    int shift = 24 - 8*pass;
    unsigned hm = pass ? (0xFFFFFFFFu << (shift+8)) : 0u;
    hist[tid] = 0;
    __syncthreads();
    for (int idx=tid; idx<WROW; idx+=256){
      unsigned u = row[idx];
      if ((u & hm) == prefix) atomicAdd(&hist[(u>>shift)&0xFFu], 1u);
    }
    __syncthreads();
    if (tid==0){
      int cum = 0, b = 255;
      for (; b>=0; b--){ cum += (int)hist[b]; if (cum >= krem) break; }
      int above = cum - (int)hist[b];
      s_prefix = prefix | ((unsigned)b << shift);
      s_krem = krem - above;
    }
    __syncthreads();
    prefix = s_prefix; krem = s_krem;
    __syncthreads();
  }
  int cg = 0;
  for (int idx=tid; idx<WROW; idx+=256) if (row[idx] > prefix) cg++;
  __shared__ int csum[8];
  cg = warpSumI(cg);
  if ((tid&31)==0) csum[tid>>5] = cg;
  __syncthreads();
  if (tid==0){
    int t = 0;
    for (int w=0;w<8;w++) t += csum[w];
    g_T[m] = prefix;
    g_need[m] = KSEL - t;
  }
}

// ----------------------------------------------------------------------------
// Per m: build mask; equals-to-threshold selected in index order (stable topk)
// ----------------------------------------------------------------------------
__global__ void __launch_bounds__(256) mask_kernel(){
  int m = blockIdx.x, tid = threadIdx.x;
  unsigned T = g_T[m]; int need = g_need[m];
  const unsigned* row = g_scores + (size_t)m*WROW;
  unsigned char* mrow = g_mask + (size_t)m*WROW;
  __shared__ int running;
  __shared__ int wtot[8];
  if (tid==0) running = 0;
  __syncthreads();
  int lane = tid & 31, w = tid >> 5;
  for (int base=0; base<WROW; base+=256){
    int idx = base + tid;
    bool valid = idx < WROW;
    unsigned u = valid ? row[idx] : 0u;
    bool gt = valid && (u > T);
    bool eq = valid && (u == T);
    unsigned bal = __ballot_sync(0xffffffffu, eq);
    int lrank = __popc(bal & ((1u<<lane)-1u));
    if (lane==0) wtot[w] = __popc(bal);
    __syncthreads();
    int off = running;
    for (int ww=0; ww<w; ww++) off += wtot[ww];
    bool sel = eq && (off + lrank < need);
    if (valid) mrow[idx] = (gt || sel) ? 1 : 0;
    __syncthreads();
    if (tid==0){
      int tot = 0;
      for (int ww=0; ww<8; ww++) tot += wtot[ww];
      running += tot;
    }
    __syncthreads();
  }
}

// ----------------------------------------------------------------------------
// attn kernel: block = (m, tile of 8 query rows). masked softmax + P@V.
// ----------------------------------------------------------------------------
__global__ void __launch_bounds__(256) attn_kernel(){
  int blk = blockIdx.x;
  int m = blk / 49, it = blk % 49;
  int i0 = it*8;
  int tid = threadIdx.x, lane = tid & 31, w = tid >> 5;
  __shared__ float l[8][Nn];

  for (int idx=tid; idx<8*Nn; idx+=256){
    int i = idx/Nn, j = idx%Nn;
    int gi = i0 + i;
    float v = g_logits[((size_t)m*Nn + gi)*Nn + j];
    int same = (gi >= LF) ? LF : 0;
    int jl = j - same;
    if (jl >= 0 && jl < LF && g_mask[(size_t)m*WROW + (size_t)gi*LF + jl]) v = NEGINF;
    l[i][j] = v;
  }
  __syncthreads();

  // warp w: softmax for row i0+w
  float* li = l[w];
  float lm = -3.4e38f;
  for (int j=lane; j<Nn; j+=32) lm = fmaxf(lm, li[j]);
  float mx = warpMax(lm);
  float ls = 0.f;
  for (int j=lane; j<Nn; j+=32){ float e = expf(li[j]-mx); li[j]=e; ls+=e; }
  float sum = warpSum(ls);
  float inv = 1.0f/sum;
  for (int j=lane; j<Nn; j+=32) li[j] *= inv;
  __syncthreads();

  // output: thread (warp=i, lane=d)
  float acc = 0.f;
  const float* vb = g_v + (size_t)m*Nn*HD + lane;
  #pragma unroll 4
  for (int j=0; j<Nn; j++) acc += li[j] * vb[(size_t)j*HD];

  int b = m >> 4, h = m & 15;
  g_o[((size_t)(b*Nn + (i0+w)))*Cc + h*HD + lane] = acc;
}

// ----------------------------------------------------------------------------
// Launch
// ----------------------------------------------------------------------------
extern "C" void kernel_launch(void* const* d_in, const int* in_sizes, int n_in,
                              void* d_out, int out_size){
  const float* x      = (const float*)d_in[0];
  const float* n1w    = (const float*)d_in[1];
  const float* n1b    = (const float*)d_in[2];
  const float* qkv_w  = (const float*)d_in[3];
  const float* qkv_b  = (const float*)d_in[4];
  const float* proj_w = (const float*)d_in[5];
  const float* proj_b = (const float*)d_in[6];
  const float* n2w    = (const float*)d_in[7];
  const float* n2b    = (const float*)d_in[8];
  const float* fc1_w  = (const float*)d_in[9];
  const float* fc1_b  = (const float*)d_in[10];
  const float* fc2_w  = (const float*)d_in[11];
  const float* fc2_b  = (const float*)d_in[12];
  float* out = (float*)d_out;

  float *p_h, *p_qkv, *p_o, *p_x1, *p_h2, *p_mlp;
  cudaGetSymbolAddress((void**)&p_h,   g_h);
  cudaGetSymbolAddress((void**)&p_qkv, g_qkv);
  cudaGetSymbolAddress((void**)&p_o,   g_o);
  cudaGetSymbolAddress((void**)&p_x1,  g_x1);
  cudaGetSymbolAddress((void**)&p_h2,  g_h2);
  cudaGetSymbolAddress((void**)&p_mlp, g_mlp);

  // 1) LN1
  ln_kernel<<<ROWS, 256>>>(x, n1w, n1b, p_h);
  // 2) QKV GEMM: [6272,512] @ [512,1536]
  gemm_tf32<<<dim3(3*Cc/128, ROWS/128), 256>>>(p_h, qkv_w, qkv_b, nullptr, p_qkv,
                                               ROWS, 3*Cc, Cc, 0);
  // 3) reorder to per-head Q/K/V
  reorder_qkv<<<(ROWS*3*Cc + 255)/256, 256>>>();
  // 4) logits + dropout scores (8 query rows per block)
  score_kernel<<<Mm*49, 256>>>();
  // 5) per-m top-k threshold
  select_kernel<<<Mm, 256>>>();
  // 6) per-m mask with stable tie-break
  mask_kernel<<<Mm, 256>>>();
  // 7) masked softmax + AV (8 query rows per block)
  attn_kernel<<<Mm*49, 256>>>();
  // 8) proj + residual(x)
  gemm_tf32<<<dim3(Cc/128, ROWS/128), 256>>>(p_o, proj_w, proj_b, x, p_x1,
                                             ROWS, Cc, Cc, 0);
  // 9) LN2
  ln_kernel<<<ROWS, 256>>>(p_x1, n2w, n2b, p_h2);
  // 10) fc1 + exact gelu
  gemm_tf32<<<dim3(MLPH/128, ROWS/128), 256>>>(p_h2, fc1_w, fc1_b, nullptr, p_mlp,
                                               ROWS, MLPH, Cc, 1);
  // 11) fc2 + residual(x1) -> out
  gemm_tf32<<<dim3(Cc/128, ROWS/128), 256>>>(p_mlp, fc2_w, fc2_b, p_x1, out,
                                             ROWS, Cc, MLPH, 0);
}

// round 3
// speedup vs baseline: 2.0159x; 1.0759x over previous
#include <cuda_runtime.h>
#include <cuda_bf16.h>
#include <math.h>

// ----------------------------------------------------------------------------
// Problem constants
// ----------------------------------------------------------------------------
#define Bz   16
#define Nn   392
#define Cc   512
#define Hh   16
#define HD   32
#define Mm   (Bz*Hh)          // 256
#define LF   196              // Nn/2
#define MLPH 2048
#define ROWS (Bz*Nn)          // 6272
#define WROW (Nn*LF)          // 76832  scores per m
#define KSEL 7448             // int(0.1*195)*392
#define NEGINF __int_as_float(0xff800000)

// ----------------------------------------------------------------------------
// Scratch (static device globals; no allocation at runtime)
// ----------------------------------------------------------------------------
__device__ float g_h   [ROWS*Cc];
__device__ float g_qkv [ROWS*3*Cc];
__device__ float g_q   [Mm*Nn*HD];
__device__ float g_k   [Mm*Nn*HD];
__device__ float g_v   [Mm*Nn*HD];
__device__ float g_logits[(size_t)Mm*Nn*Nn];
__device__ unsigned g_scores[(size_t)Mm*WROW];
__device__ unsigned char g_mask[(size_t)Mm*WROW];
__device__ float g_o   [ROWS*Cc];
__device__ float g_x1  [ROWS*Cc];
__device__ float g_h2  [ROWS*Cc];
__device__ float g_mlp [ROWS*MLPH];
__device__ unsigned g_T[Mm];
__device__ int g_need[Mm];

// ----------------------------------------------------------------------------
// Reductions
// ----------------------------------------------------------------------------
__device__ __forceinline__ float warpMax(float v){
  #pragma unroll
  for (int o=16;o>0;o>>=1) v = fmaxf(v, __shfl_xor_sync(0xffffffffu, v, o));
  return v;
}
__device__ __forceinline__ float warpSum(float v){
  #pragma unroll
  for (int o=16;o>0;o>>=1) v += __shfl_xor_sync(0xffffffffu, v, o);
  return v;
}
__device__ __forceinline__ int warpSumI(int v){
  #pragma unroll
  for (int o=16;o>0;o>>=1) v += __shfl_xor_sync(0xffffffffu, v, o);
  return v;
}
template<int NW>
__device__ __forceinline__ float blockSum(float v, float* sw){
  int lane = threadIdx.x & 31, w = threadIdx.x >> 5;
  v = warpSum(v);
  if (lane==0) sw[w] = v;
  __syncthreads();
  float r = 0.f;
  #pragma unroll
  for (int i=0;i<NW;i++) r += sw[i];
  __syncthreads();
  return r;
}

// ----------------------------------------------------------------------------
// JAX threefry2x32, key (0,42), partitionable 32-bit path
// ----------------------------------------------------------------------------
__device__ __forceinline__ unsigned rotl32(unsigned x, int r){ return (x<<r)|(x>>(32-r)); }
__device__ __forceinline__ unsigned threefry_bits(unsigned idx){
  const unsigned k0 = 0u, k1 = 42u;
  const unsigned k2 = k0 ^ k1 ^ 0x1BD11BDAu;
  unsigned x0 = 0u + k0;
  unsigned x1 = idx + k1;
#define TFR(r) { x0 += x1; x1 = rotl32(x1,(r)); x1 ^= x0; }
  TFR(13) TFR(15) TFR(26) TFR(6)
  x0 += k1; x1 += k2 + 1u;
  TFR(17) TFR(29) TFR(16) TFR(24)
  x0 += k2; x1 += k0 + 2u;
  TFR(13) TFR(15) TFR(26) TFR(6)
  x0 += k0; x1 += k1 + 3u;
  TFR(17) TFR(29) TFR(16) TFR(24)
  x0 += k1; x1 += k2 + 4u;
  TFR(13) TFR(15) TFR(26) TFR(6)
  x0 += k2; x1 += k0 + 5u;
#undef TFR
  return x0 ^ x1;
}
__device__ __forceinline__ float gumbel_at(unsigned idx){
  unsigned bits = threefry_bits(idx);
  float f = __uint_as_float((bits >> 9) | 0x3f800000u) - 1.0f;
  const float tiny = 1.17549435e-38f;
  float u = fmaxf(tiny, f + tiny);
  return -__logf(-__logf(u));
}

// ----------------------------------------------------------------------------
// LayerNorm (one block per row, 256 threads, C=512)
// ----------------------------------------------------------------------------
__global__ void __launch_bounds__(256) ln_kernel(const float* __restrict__ x,
                                                 const float* __restrict__ w,
                                                 const float* __restrict__ bias,
                                                 float* __restrict__ out){
  int row = blockIdx.x, t = threadIdx.x;
  const float* xr = x + (size_t)row*Cc;
  __shared__ float sw[8];
  float a = xr[t], b = xr[t+256];
  float s = blockSum<8>(a+b, sw);
  float mu = s * (1.0f/512.0f);
  float da = a-mu, db = b-mu;
  float v = blockSum<8>(da*da + db*db, sw);
  float rstd = rsqrtf(v*(1.0f/512.0f) + 1e-5f);
  out[(size_t)row*Cc + t]     = da*rstd*w[t]     + bias[t];
  out[(size_t)row*Cc + t+256] = db*rstd*w[t+256] + bias[t+256];
}

// ----------------------------------------------------------------------------
// tf32 tensor-core GEMM: C[M,N] = A[M,K] @ B[K,N] + bias (+gelu) (+residual)
// 128x128 tile, BK=16, 256 threads (8 warps, 2x4), mma.m16n8k8.tf32,
// cp.async double-buffered. A smem pad 20, B smem pad 136.
// ----------------------------------------------------------------------------
__device__ __forceinline__ void cp16(float* dst, const float* src){
  unsigned d = (unsigned)__cvta_generic_to_shared(dst);
  asm volatile("cp.async.ca.shared.global [%0], [%1], 16;\n" :: "r"(d), "l"(src));
}
__device__ __forceinline__ unsigned f2tf(float x){
  unsigned r; asm("cvt.rna.tf32.f32 %0, %1;\n":"=r"(r):"f"(x)); return r;
}
__device__ __forceinline__ void mma_tf32(float* c, const unsigned* a, const unsigned* b){
  asm volatile(
    "mma.sync.aligned.m16n8k8.row.col.f32.tf32.tf32.f32 "
    "{%0,%1,%2,%3},{%4,%5,%6,%7},{%8,%9},{%0,%1,%2,%3};\n"
    : "+f"(c[0]),"+f"(c[1]),"+f"(c[2]),"+f"(c[3])
    : "r"(a[0]),"r"(a[1]),"r"(a[2]),"r"(a[3]),"r"(b[0]),"r"(b[1]));
}

#define APAD 20
#define BPAD 136

__global__ void __launch_bounds__(256, 2) gemm_tf32(const float* __restrict__ A,
                                                 const float* __restrict__ Bw,
                                                 const float* __restrict__ bias,
                                                 const float* __restrict__ res,
                                                 float* __restrict__ C,
                                                 int M, int N, int K, int act){
  __shared__ float As[2][128*APAD];
  __shared__ float Bs[2][16*BPAD];
  const int tid = threadIdx.x;
  const int lane = tid & 31, wid = tid >> 5;
  const int wm = wid >> 2, wn = wid & 3;       // 2 x 4 warp grid
  const int bm = blockIdx.y*128, bn = blockIdx.x*128;

  float acc[16][4];
  #pragma unroll
  for (int i=0;i<16;i++){ acc[i][0]=0.f; acc[i][1]=0.f; acc[i][2]=0.f; acc[i][3]=0.f; }

  const int nT = K >> 4;

  // ---- stage loader
  auto load_stage = [&](int t, int buf){
    int k0 = t << 4;
    #pragma unroll
    for (int r=0;r<2;r++){
      int i = tid + 256*r;
      int arow = i >> 2, ac = (i & 3) << 2;
      cp16(&As[buf][arow*APAD + ac], A + (size_t)(bm+arow)*K + k0 + ac);
      int brow = i >> 5, bc = (i & 31) << 2;
      cp16(&Bs[buf][brow*BPAD + bc], Bw + (size_t)(k0+brow)*N + bn + bc);
    }
    asm volatile("cp.async.commit_group;\n");
  };

  load_stage(0, 0);
  for (int t=0; t<nT; t++){
    if (t+1 < nT) load_stage(t+1, (t+1)&1);
    if (t+1 < nT) asm volatile("cp.async.wait_group 1;\n");
    else          asm volatile("cp.async.wait_group 0;\n");
    __syncthreads();
    const float* as = As[t&1];
    const float* bs = Bs[t&1];
    #pragma unroll
    for (int ks=0; ks<16; ks+=8){
      unsigned a[4][4], b[4][2];
      #pragma unroll
      for (int mt=0;mt<4;mt++){
        int r0 = wm*64 + mt*16 + (lane>>2);
        int cc = ks + (lane&3);
        a[mt][0] = f2tf(as[r0*APAD + cc]);
        a[mt][1] = f2tf(as[(r0+8)*APAD + cc]);
        a[mt][2] = f2tf(as[r0*APAD + cc + 4]);
        a[mt][3] = f2tf(as[(r0+8)*APAD + cc + 4]);
      }
      #pragma unroll
      for (int nt=0;nt<4;nt++){
        int cn = wn*32 + nt*8 + (lane>>2);
        b[nt][0] = f2tf(bs[(ks + (lane&3))*BPAD + cn]);
        b[nt][1] = f2tf(bs[(ks + 4 + (lane&3))*BPAD + cn]);
      }
      #pragma unroll
      for (int mt=0;mt<4;mt++)
        #pragma unroll
        for (int nt=0;nt<4;nt++)
          mma_tf32(acc[mt*4+nt], a[mt], b[nt]);
    }
    __syncthreads();
  }

  // ---- epilogue
  #pragma unroll
  for (int mt=0;mt<4;mt++){
    #pragma unroll
    for (int nt=0;nt<4;nt++){
      float* c = acc[mt*4+nt];
      int gm = bm + wm*64 + mt*16 + (lane>>2);
      int gn = bn + wn*32 + nt*8 + ((lane&3)<<1);
      float b0 = bias[gn], b1 = bias[gn+1];
      #pragma unroll
      for (int hrow=0; hrow<2; hrow++){
        int gr = gm + hrow*8;
        float v0 = c[hrow*2+0] + b0;
        float v1 = c[hrow*2+1] + b1;
        if (act==1){
          v0 = 0.5f*v0*(1.0f + erff(v0*0.70710678118654752440f));
          v1 = 0.5f*v1*(1.0f + erff(v1*0.70710678118654752440f));
        }
        if (res){
          v0 += res[(size_t)gr*N + gn];
          v1 += res[(size_t)gr*N + gn+1];
        }
        C[(size_t)gr*N + gn]   = v0;
        C[(size_t)gr*N + gn+1] = v1;
      }
    }
  }
}

// ----------------------------------------------------------------------------
// QKV reorder: [row=b*392+i][3*512] -> Q/K/V [m=b*16+h][i][d]
// ----------------------------------------------------------------------------
__global__ void reorder_qkv(){
  int idx = blockIdx.x*blockDim.x + threadIdx.x;
  if (idx >= ROWS*3*Cc) return;
  int r = idx / (3*Cc), c = idx % (3*Cc);
  int which = c >> 9;
  int cc = c & 511;
  int h = cc >> 5, d = cc & 31;
  int b = r / Nn, i = r % Nn;
  float v = g_qkv[idx];
  size_t dst = ((size_t)((b*Hh+h)*Nn + i))*HD + d;
  if (which==0) g_q[dst]=v; else if (which==1) g_k[dst]=v; else g_v[dst]=v;
}

// ----------------------------------------------------------------------------
// score kernel: block = (m, tile of 8 query rows). K read once per tile.
// Register-lean dot loop, MUFU transcendentals, occupancy >= 3 CTA/SM.
// ----------------------------------------------------------------------------
__global__ void __launch_bounds__(256, 3) score_kernel(){
  int blk = blockIdx.x;
  int m = blk / 49, it = blk % 49;
  int i0 = it*8;
  int tid = threadIdx.x, lane = tid & 31, w = tid >> 5;
  __shared__ float q[8][32];
  __shared__ float l[8][Nn];

  { // load 8 q rows
    int i = tid >> 5, d = tid & 31;
    q[i][d] = g_q[((size_t)m*Nn + i0 + i)*HD + d];
  }
  __syncthreads();

  const float scale = 0.17677669529663687f; // 32^-0.5
  #pragma unroll 1
  for (int j=tid; j<Nn; j+=256){
    const float4* kp = (const float4*)(g_k + ((size_t)m*Nn + j)*HD);
    float acc[8];
    #pragma unroll
    for (int i=0;i<8;i++) acc[i]=0.f;
    #pragma unroll
    for (int t=0;t<8;t++){
      float4 kv = kp[t];
      #pragma unroll
      for (int i=0;i<8;i++){
        float4 qv = ((const float4*)q[i])[t];
        acc[i] += kv.x*qv.x + kv.y*qv.y + kv.z*qv.z + kv.w*qv.w;
      }
    }
    #pragma unroll
    for (int i=0;i<8;i++) l[i][j] = acc[i]*scale;
  }
  __syncthreads();

  // dump logits
  #pragma unroll 1
  for (int idx=tid; idx<8*Nn; idx+=256){
    int i = idx/Nn, j = idx%Nn;
    g_logits[((size_t)m*Nn + i0 + i)*Nn + j] = l[i][j];
  }
  __syncthreads();

  // per-warp stats (warp w owns row i0+w)
  int i = i0 + w;
  float* li = l[w];
  float lm = -3.4e38f;
  #pragma unroll 1
  for (int j=lane; j<Nn; j+=32) lm = fmaxf(lm, li[j]);
  float mx = warpMax(lm);
  float ls = 0.f;
  #pragma unroll 1
  for (int j=lane; j<Nn; j+=32) ls += __expf(li[j]-mx);
  float inv_sum = 1.0f/warpSum(ls);

  int side = (i >= LF);
  int same = side ? LF : 0;
  int cross = side ? 0 : LF;
  float cm = -3.4e38f;
  #pragma unroll 1
  for (int jl=lane; jl<LF; jl+=32) cm = fmaxf(cm, li[cross+jl]);
  float cmx = warpMax(cm);
  float aqmax = __expf(cmx - mx)*inv_sum + 1e-6f;

  int diag = i - same;
  // pass 1: sp = (diag?0:s+1e-6), cache into li[same+jl], accumulate sum
  float ssum = 0.f;
  #pragma unroll 1
  for (int jl=lane; jl<LF; jl+=32){
    float s = __expf(li[same+jl]-mx)*inv_sum;
    float sp = (jl==diag) ? 0.f : (s + 1e-6f);
    li[same+jl] = sp;
    ssum += sp;
  }
  float invS = 1.0f/warpSum(ssum);
  float rowc = aqmax*invS;

  // pass 2: score = log(sp*rowc) + gumbel
  #pragma unroll 1
  for (int jl=lane; jl<LF; jl+=32){
    float sc;
    if (jl==diag) sc = NEGINF;
    else {
      float wv = li[same+jl]*rowc;
      unsigned gi = (unsigned)(m*WROW + i*LF + jl);
      sc = __logf(wv) + gumbel_at(gi);
    }
    unsigned bb = __float_as_uint(sc);
    bb = (bb & 0x80000000u) ? ~bb : (bb | 0x80000000u);
    g_scores[(size_t)m*WROW + (size_t)i*LF + jl] = bb;
  }
}

// ----------------------------------------------------------------------------
// Per m: radix-select the KSEL-th largest score, count > T
// ----------------------------------------------------------------------------
__global__ void __launch_bounds__(256) select_kernel(){
  int m = blockIdx.x, tid = threadIdx.x;
  const unsigned* row = g_scores + (size_t)m*WROW;
  __shared__ unsigned hist[256];
  __shared__ unsigned s_prefix;
  __shared__ int s_krem;
  unsigned prefix = 0; int krem = KSEL;
  for (int pass=0; pass<4; pass++){
    int shift = 24 - 8*pass;
    unsigned hm = pass ? (0xFFFFFFFFu << (shift+8)) : 0u;
    hist[tid] = 0;
    __syncthreads();
    for (int idx=tid; idx<WROW; idx+=256){
      unsigned u = row[idx];
      if ((u & hm) == prefix) atomicAdd(&hist[(u>>shift)&0xFFu], 1u);
    }
    __syncthreads();
    if (tid==0){
      int cum = 0, b = 255;
      for (; b>=0; b--){ cum += (int)hist[b]; if (cum >= krem) break; }
      int above = cum - (int)hist[b];
      s_prefix = prefix | ((unsigned)b << shift);
      s_krem = krem - above;
    }
    __syncthreads();
    prefix = s_prefix; krem = s_krem;
    __syncthreads();
  }
  int cg = 0;
  for (int idx=tid; idx<WROW; idx+=256) if (row[idx] > prefix) cg++;
  __shared__ int csum[8];
  cg = warpSumI(cg);
  if ((tid&31)==0) csum[tid>>5] = cg;
  __syncthreads();
  if (tid==0){
    int t = 0;
    for (int w=0;w<8;w++) t += csum[w];
    g_T[m] = prefix;
    g_need[m] = KSEL - t;
  }
}

// ----------------------------------------------------------------------------
// Per m: build mask; equals-to-threshold selected in index order (stable topk)
// ----------------------------------------------------------------------------
__global__ void __launch_bounds__(256) mask_kernel(){
  int m = blockIdx.x, tid = threadIdx.x;
  unsigned T = g_T[m]; int need = g_need[m];
  const unsigned* row = g_scores + (size_t)m*WROW;
  unsigned char* mrow = g_mask + (size_t)m*WROW;
  __shared__ int running;
  __shared__ int wtot[8];
  if (tid==0) running = 0;
  __syncthreads();
  int lane = tid & 31, w = tid >> 5;
  for (int base=0; base<WROW; base+=256){
    int idx = base + tid;
    bool valid = idx < WROW;
    unsigned u = valid ? row[idx] : 0u;
    bool gt = valid && (u > T);
    bool eq = valid && (u == T);
    unsigned bal = __ballot_sync(0xffffffffu, eq);
    int lrank = __popc(bal & ((1u<<lane)-1u));
    if (lane==0) wtot[w] = __popc(bal);
    __syncthreads();
    int off = running;
    for (int ww=0; ww<w; ww++) off += wtot[ww];
    bool sel = eq && (off + lrank < need);
    if (valid) mrow[idx] = (gt || sel) ? 1 : 0;
    __syncthreads();
    if (tid==0){
      int tot = 0;
      for (int ww=0; ww<8; ww++) tot += wtot[ww];
      running += tot;
    }
    __syncthreads();
  }
}

// ----------------------------------------------------------------------------
// attn kernel: block = (m, tile of 8 query rows). masked softmax + P@V.
// ----------------------------------------------------------------------------
__global__ void __launch_bounds__(256, 4) attn_kernel(){
  int blk = blockIdx.x;
  int m = blk / 49, it = blk % 49;
  int i0 = it*8;
  int tid = threadIdx.x, lane = tid & 31, w = tid >> 5;
  __shared__ float l[8][Nn];

  #pragma unroll 1
  for (int idx=tid; idx<8*Nn; idx+=256){
    int i = idx/Nn, j = idx%Nn;
    int gi = i0 + i;
    float v = g_logits[((size_t)m*Nn + gi)*Nn + j];
    int same = (gi >= LF) ? LF : 0;
    int jl = j - same;
    if (jl >= 0 && jl < LF && g_mask[(size_t)m*WROW + (size_t)gi*LF + jl]) v = NEGINF;
    l[i][j] = v;
  }
  __syncthreads();

  // warp w: softmax for row i0+w
  float* li = l[w];
  float lm = -3.4e38f;
  #pragma unroll 1
  for (int j=lane; j<Nn; j+=32) lm = fmaxf(lm, li[j]);
  float mx = warpMax(lm);
  float ls = 0.f;
  #pragma unroll 1
  for (int j=lane; j<Nn; j+=32){ float e = __expf(li[j]-mx); li[j]=e; ls+=e; }
  float sum = warpSum(ls);
  float inv = 1.0f/sum;
  #pragma unroll 1
  for (int j=lane; j<Nn; j+=32) li[j] *= inv;
  __syncthreads();

  // output: thread (warp=i, lane=d)
  float acc = 0.f;
  const float* vb = g_v + (size_t)m*Nn*HD + lane;
  #pragma unroll 4
  for (int j=0; j<Nn; j++) acc += li[j] * vb[(size_t)j*HD];

  int b = m >> 4, h = m & 15;
  g_o[((size_t)(b*Nn + (i0+w)))*Cc + h*HD + lane] = acc;
}

// ----------------------------------------------------------------------------
// Launch
// ----------------------------------------------------------------------------
extern "C" void kernel_launch(void* const* d_in, const int* in_sizes, int n_in,
                              void* d_out, int out_size){
  const float* x      = (const float*)d_in[0];
  const float* n1w    = (const float*)d_in[1];
  const float* n1b    = (const float*)d_in[2];
  const float* qkv_w  = (const float*)d_in[3];
  const float* qkv_b  = (const float*)d_in[4];
  const float* proj_w = (const float*)d_in[5];
  const float* proj_b = (const float*)d_in[6];
  const float* n2w    = (const float*)d_in[7];
  const float* n2b    = (const float*)d_in[8];
  const float* fc1_w  = (const float*)d_in[9];
  const float* fc1_b  = (const float*)d_in[10];
  const float* fc2_w  = (const float*)d_in[11];
  const float* fc2_b  = (const float*)d_in[12];
  float* out = (float*)d_out;

  float *p_h, *p_qkv, *p_o, *p_x1, *p_h2, *p_mlp;
  cudaGetSymbolAddress((void**)&p_h,   g_h);
  cudaGetSymbolAddress((void**)&p_qkv, g_qkv);
  cudaGetSymbolAddress((void**)&p_o,   g_o);
  cudaGetSymbolAddress((void**)&p_x1,  g_x1);
  cudaGetSymbolAddress((void**)&p_h2,  g_h2);
  cudaGetSymbolAddress((void**)&p_mlp, g_mlp);

  // 1) LN1
  ln_kernel<<<ROWS, 256>>>(x, n1w, n1b, p_h);
  // 2) QKV GEMM: [6272,512] @ [512,1536]
  gemm_tf32<<<dim3(3*Cc/128, ROWS/128), 256>>>(p_h, qkv_w, qkv_b, nullptr, p_qkv,
                                               ROWS, 3*Cc, Cc, 0);
  // 3) reorder to per-head Q/K/V
  reorder_qkv<<<(ROWS*3*Cc + 255)/256, 256>>>();
  // 4) logits + dropout scores (8 query rows per block)
  score_kernel<<<Mm*49, 256>>>();
  // 5) per-m top-k threshold
  select_kernel<<<Mm, 256>>>();
  // 6) per-m mask with stable tie-break
  mask_kernel<<<Mm, 256>>>();
  // 7) masked softmax + AV (8 query rows per block)
  attn_kernel<<<Mm*49, 256>>>();
  // 8) proj + residual(x)
  gemm_tf32<<<dim3(Cc/128, ROWS/128), 256>>>(p_o, proj_w, proj_b, x, p_x1,
                                             ROWS, Cc, Cc, 0);
  // 9) LN2
  ln_kernel<<<ROWS, 256>>>(p_x1, n2w, n2b, p_h2);
  // 10) fc1 + exact gelu
  gemm_tf32<<<dim3(MLPH/128, ROWS/128), 256>>>(p_h2, fc1_w, fc1_b, nullptr, p_mlp,
                                               ROWS, MLPH, Cc, 1);
  // 11) fc2 + residual(x1) -> out
  gemm_tf32<<<dim3(Cc/128, ROWS/128), 256>>>(p_mlp, fc2_w, fc2_b, p_x1, out,
                                             ROWS, Cc, MLPH, 0);
}